// round 13
// baseline (speedup 1.0000x reference)
#include <cuda_runtime.h>
#include <cuda_bf16.h>
#include <math.h>
#include <stdint.h>

// Problem constants
#define Bc 4
#define Sc 2048
#define Dc 768
#define Hc 12
#define DHc 64
#define Fc 3072
#define Lc 4
#define Mc (Bc*Sc)   // 8192 rows
#define QKVc 2304    // 3*Dc

// ---------------------------------------------------------------------------
// Scratch (device globals; no allocation allowed)
// ---------------------------------------------------------------------------
__device__ float g_x[(size_t)Mc*Dc];
__device__ float g_proj[(size_t)Mc*Dc];
__device__ float g_h[(size_t)Mc*Dc];
__device__ float g_f2[(size_t)Mc*Dc];

__device__ __nv_bfloat16 g_acth[(size_t)Mc*Dc];
__device__ __nv_bfloat16 g_actl[(size_t)Mc*Dc];
__device__ __nv_bfloat16 g_qkvh[(size_t)Mc*QKVc];
__device__ __nv_bfloat16 g_qkvl[(size_t)Mc*QKVc];
__device__ __nv_bfloat16 g_f1h[(size_t)Mc*Fc];
__device__ __nv_bfloat16 g_f1l[(size_t)Mc*Fc];

#define WT_PER_LAYER ((size_t)4*Dc*Dc + 2*(size_t)Dc*Fc)
__device__ __nv_bfloat16 g_wt_hi[WT_PER_LAYER*Lc];
__device__ __nv_bfloat16 g_wt_lo[WT_PER_LAYER*Lc];

// ---------------------------------------------------------------------------
// Helpers
// ---------------------------------------------------------------------------
__device__ __forceinline__ uint32_t smem_u32(const void* p){
    uint32_t a;
    asm("{ .reg .u64 t; cvta.to.shared.u64 t, %1; cvt.u32.u64 %0, t; }":"=r"(a):"l"(p));
    return a;
}
__device__ __forceinline__ void cpasync16(uint32_t dst, const void* src){
    asm volatile("cp.async.cg.shared.global [%0], [%1], 16;" :: "r"(dst), "l"(src));
}
#define CP_COMMIT() asm volatile("cp.async.commit_group;" ::: "memory")

__device__ __forceinline__ void ldm_x4(uint32_t addr, uint32_t& r0, uint32_t& r1,
                                       uint32_t& r2, uint32_t& r3){
    asm volatile("ldmatrix.sync.aligned.m8n8.x4.shared.b16 {%0,%1,%2,%3}, [%4];"
        : "=r"(r0),"=r"(r1),"=r"(r2),"=r"(r3) : "r"(addr));
}
__device__ __forceinline__ void ldm_x2(uint32_t addr, uint32_t& r0, uint32_t& r1){
    asm volatile("ldmatrix.sync.aligned.m8n8.x2.shared.b16 {%0,%1}, [%2];"
        : "=r"(r0),"=r"(r1) : "r"(addr));
}
__device__ __forceinline__ void ldm_x4_t(uint32_t addr, uint32_t& r0, uint32_t& r1,
                                         uint32_t& r2, uint32_t& r3){
    asm volatile("ldmatrix.sync.aligned.m8n8.x4.trans.shared.b16 {%0,%1,%2,%3}, [%4];"
        : "=r"(r0),"=r"(r1),"=r"(r2),"=r"(r3) : "r"(addr));
}
__device__ __forceinline__ void mma_bf16(float* c, const uint32_t* a, const uint32_t* b){
    asm volatile("mma.sync.aligned.m16n8k16.row.col.f32.bf16.bf16.f32 "
        "{%0,%1,%2,%3}, {%4,%5,%6,%7}, {%8,%9}, {%0,%1,%2,%3};"
        : "+f"(c[0]),"+f"(c[1]),"+f"(c[2]),"+f"(c[3])
        : "r"(a[0]),"r"(a[1]),"r"(a[2]),"r"(a[3]), "r"(b[0]),"r"(b[1]));
}
__device__ __forceinline__ uint32_t pack_bf2(__nv_bfloat16 a, __nv_bfloat16 b){
    union { __nv_bfloat162 v; uint32_t u; } t;
    t.v.x = a; t.v.y = b; return t.u;
}
__device__ __forceinline__ uint32_t split_pack(float v0, float v1, uint32_t& lo){
    __nv_bfloat16 h0 = __float2bfloat16(v0);
    __nv_bfloat16 h1 = __float2bfloat16(v1);
    lo = pack_bf2(__float2bfloat16(v0 - __bfloat162float(h0)),
                  __float2bfloat16(v1 - __bfloat162float(h1)));
    return pack_bf2(h0, h1);
}

// ---------------------------------------------------------------------------
// mma.sync GEMM (3-term bf16 split), templated M-tile: BM = 32*IM.
// 8 warps (2 x 4); warp tile (IM*16) x 32; BN=128, BK=32; 2-stage cp.async.
// IM=4: BM=128 (stage 40KB). IM=2: BM=64 (stage 30KB). Both: 2 CTAs/SM.
// ---------------------------------------------------------------------------
#define T_STRIDE 80
#define BTILE_B  (128*T_STRIDE)                 // 10240 per B array

template<int IM>
__global__ void __launch_bounds__(256, 2) gemm_tc_t(
    const __nv_bfloat16* __restrict__ Ah, const __nv_bfloat16* __restrict__ Al,
    const __nv_bfloat16* __restrict__ Bh, const __nv_bfloat16* __restrict__ Bl,
    const float* __restrict__ bias,
    float* __restrict__ Cf,
    __nv_bfloat16* __restrict__ Ch, __nv_bfloat16* __restrict__ Cl,
    int M, int N, int K, int ldc, int epi)
{
    constexpr int AROWS   = 32*IM;               // BM
    constexpr int ATILE_B = AROWS*T_STRIDE;      // bytes per A array
    constexpr int STAGE   = 2*ATILE_B + 2*BTILE_B;
    constexpr int NA = AROWS*4;                  // 16B chunks per A array
    constexpr int NB = 128*4;
    constexpr int TOT = 2*NA + 2*NB;

    extern __shared__ char smem[];
    const uint32_t sbase = smem_u32(smem);
    const int tid = threadIdx.x;
    const int wid = tid >> 5, lane = tid & 31;
    const int warpM = wid >> 2, warpN = wid & 3;
    const int m0 = blockIdx.y * AROWS, n0 = blockIdx.x * 128;

    auto load_chunk = [&](int c, int s){
        const int k0 = c * 32;
        #pragma unroll
        for (int i = 0; i < TOT/256; i++){
            int idx = tid + i*256;
            uint32_t dst; const char* src;
            if (idx < 2*NA){
                int arr = idx / NA, rem = idx - arr*NA;
                int row = rem >> 2, seg = rem & 3;
                const __nv_bfloat16* P = arr ? Al : Ah;
                src = (const char*)(P + (size_t)(m0 + row)*K + k0) + seg*16;
                dst = sbase + s*STAGE + arr*ATILE_B + row*T_STRIDE + seg*16;
            } else {
                int idx2 = idx - 2*NA;
                int arr = idx2 / NB, rem = idx2 - arr*NB;
                int row = rem >> 2, seg = rem & 3;
                const __nv_bfloat16* P = arr ? Bl : Bh;
                src = (const char*)(P + (size_t)(n0 + row)*K + k0) + seg*16;
                dst = sbase + s*STAGE + 2*ATILE_B + arr*BTILE_B + row*T_STRIDE + seg*16;
            }
            cpasync16(dst, src);
        }
        CP_COMMIT();
    };

    float acc[IM][4][4];
    #pragma unroll
    for (int i = 0; i < IM; i++)
        #pragma unroll
        for (int j = 0; j < 4; j++)
            #pragma unroll
            for (int r = 0; r < 4; r++) acc[i][j][r] = 0.f;

    const int NC = K / 32;
    load_chunk(0, 0);

    const uint32_t aoff = (uint32_t)(lane & 15) * T_STRIDE + (uint32_t)(lane >> 4) * 16;
    const uint32_t boff = (uint32_t)(lane & 7)  * T_STRIDE + (uint32_t)((lane >> 3) & 1) * 16;

    for (int c = 0; c < NC; c++){
        const int s = c & 1;
        if (c + 1 < NC){ load_chunk(c + 1, s ^ 1); }
        if (c + 1 < NC) asm volatile("cp.async.wait_group 1;" ::: "memory");
        else            asm volatile("cp.async.wait_group 0;" ::: "memory");
        __syncthreads();

        const uint32_t st  = sbase + s*STAGE;
        const uint32_t A_h = st,              A_l = st + ATILE_B;
        const uint32_t B_h = st + 2*ATILE_B,  B_l = B_h + BTILE_B;

        #pragma unroll
        for (int ks = 0; ks < 2; ks++){
            uint32_t bh[4][2], bl[4][2];
            #pragma unroll
            for (int j = 0; j < 4; j++){
                uint32_t rb = (uint32_t)(warpN*32 + j*8) * T_STRIDE + (uint32_t)(ks*32) + boff;
                ldm_x2(B_h + rb, bh[j][0], bh[j][1]);
                ldm_x2(B_l + rb, bl[j][0], bl[j][1]);
            }
            #pragma unroll
            for (int i = 0; i < IM; i++){
                uint32_t ah4[4], al4[4];
                uint32_t ra = (uint32_t)(warpM*(IM*16) + i*16) * T_STRIDE + (uint32_t)(ks*32) + aoff;
                ldm_x4(A_h + ra, ah4[0], ah4[1], ah4[2], ah4[3]);
                ldm_x4(A_l + ra, al4[0], al4[1], al4[2], al4[3]);
                #pragma unroll
                for (int j = 0; j < 4; j++){
                    mma_bf16(acc[i][j], ah4, bh[j]);
                    mma_bf16(acc[i][j], ah4, bl[j]);
                    mma_bf16(acc[i][j], al4, bh[j]);
                }
            }
        }
        __syncthreads();
    }

    const int gid = lane >> 2, tig = lane & 3;
    #pragma unroll
    for (int i = 0; i < IM; i++){
        #pragma unroll
        for (int j = 0; j < 4; j++){
            const int col = n0 + warpN*32 + j*8 + tig*2;
            float b0 = bias ? bias[col]     : 0.f;
            float b1 = bias ? bias[col + 1] : 0.f;
            #pragma unroll
            for (int half = 0; half < 2; half++){
                const int row = m0 + warpM*(IM*16) + i*16 + gid + half*8;
                float v0 = acc[i][j][half*2 + 0] + b0;
                float v1 = acc[i][j][half*2 + 1] + b1;
                if (epi){
                    v0 = 0.5f * v0 * (1.0f + erff(v0 * 0.70710678118654752f));
                    v1 = 0.5f * v1 * (1.0f + erff(v1 * 0.70710678118654752f));
                }
                const size_t off = (size_t)row * ldc + col;
                if (Cf) *(float2*)(Cf + off) = make_float2(v0, v1);
                if (Ch){
                    uint32_t lo, hi = split_pack(v0, v1, lo);
                    *(uint32_t*)(Ch + off) = hi;
                    *(uint32_t*)(Cl + off) = lo;
                }
            }
        }
    }
}

#define GSM4 (2*(2*(128*T_STRIDE) + 2*BTILE_B))   // 81920
#define GSM2 (2*(2*(64*T_STRIDE)  + 2*BTILE_B))   // 61440

// ---------------------------------------------------------------------------
// Flash attention via mma.sync (causal) — unchanged from R12
// ---------------------------------------------------------------------------
#define AT_STRIDE 144
#define KV_STAGE  36864
#define FQ_H      36864
#define FQ_L      46080
#define FA2_SMEM  73728

__global__ void __launch_bounds__(128) flash_attn_mma(
    const __nv_bfloat16* __restrict__ qkvh, const __nv_bfloat16* __restrict__ qkvl,
    __nv_bfloat16* __restrict__ aoh, __nv_bfloat16* __restrict__ aol)
{
    extern __shared__ char smem[];
    const uint32_t sbase = smem_u32(smem);
    const int tid = threadIdx.x;
    const int wid = tid >> 5, lane = tid & 31;
    const int gid = lane >> 2, tig = lane & 3;
    const int bh = blockIdx.y;
    const int b = bh / Hc, h = bh - b*Hc;
    const int qt = (int)gridDim.x - 1 - (int)blockIdx.x;
    const int q0 = qt * 64;
    const size_t rowb = (size_t)b * Sc;
    const int qcol = h*64, kcol = Dc + h*64, vcol = 2*Dc + h*64;

    auto load_kv = [&](int kt, int s){
        const int k0 = kt * 64;
        const __nv_bfloat16* srcs[4] = {qkvh, qkvl, qkvh, qkvl};
        const int cols[4] = {kcol, kcol, vcol, vcol};
        #pragma unroll
        for (int i = 0; i < 16; i++){
            int idx = tid + i*128;
            int arr = idx >> 9;
            int rem = idx & 511;
            int row = rem >> 3, ch = rem & 7;
            const char* src = (const char*)(srcs[arr] + (rowb + k0 + row)*QKVc + cols[arr]) + ch*16;
            cpasync16(sbase + s*KV_STAGE + arr*9216 + row*AT_STRIDE + ch*16, src);
        }
        CP_COMMIT();
    };

    {
        #pragma unroll
        for (int i = 0; i < 8; i++){
            int idx = tid + i*128;
            int arr = idx >> 9;
            int rem = idx & 511;
            int row = rem >> 3, ch = rem & 7;
            const __nv_bfloat16* sp = arr ? qkvl : qkvh;
            const char* src = (const char*)(sp + (rowb + q0 + row)*QKVc + qcol) + ch*16;
            cpasync16(sbase + (arr ? FQ_L : FQ_H) + row*AT_STRIDE + ch*16, src);
        }
        load_kv(0, 0);
    }
    asm volatile("cp.async.wait_group 0;" ::: "memory");
    __syncthreads();

    uint32_t qhf[4][4], qlf[4][4];
    {
        const uint32_t ao_ = (uint32_t)(lane & 15)*AT_STRIDE + (uint32_t)(lane >> 4)*16;
        #pragma unroll
        for (int ks = 0; ks < 4; ks++){
            uint32_t ra = (uint32_t)(wid*16)*AT_STRIDE + (uint32_t)(ks*32) + ao_;
            ldm_x4(sbase + FQ_H + ra, qhf[ks][0], qhf[ks][1], qhf[ks][2], qhf[ks][3]);
            ldm_x4(sbase + FQ_L + ra, qlf[ks][0], qlf[ks][1], qlf[ks][2], qlf[ks][3]);
        }
    }
    __syncthreads();

    float accO[8][4];
    #pragma unroll
    for (int j = 0; j < 8; j++)
        #pragma unroll
        for (int c = 0; c < 4; c++) accO[j][c] = 0.f;
    float m_run[2] = {-1e30f, -1e30f};
    float l_run[2] = {0.f, 0.f};

    const uint32_t boff4 = (uint32_t)((lane & 7) + ((lane >> 4) << 3))*AT_STRIDE
                         + (uint32_t)((lane >> 3) & 1)*16;
    const uint32_t voff4 = (uint32_t)(lane & 15)*AT_STRIDE + (uint32_t)(lane >> 4)*16;

    const int row0 = q0 + wid*16 + gid;
    const int row1 = row0 + 8;

    for (int kt = 0; kt <= qt; kt++){
        const int s = kt & 1;
        if (kt > 0){
            asm volatile("cp.async.wait_group 0;" ::: "memory");
            __syncthreads();
        }
        if (kt < qt) load_kv(kt + 1, s ^ 1);

        const uint32_t K_h = sbase + s*KV_STAGE;
        const uint32_t K_l = K_h + 9216;
        const uint32_t V_h = K_h + 18432;
        const uint32_t V_l = K_h + 27648;

        float accS[8][4];
        #pragma unroll
        for (int j = 0; j < 8; j++)
            #pragma unroll
            for (int c = 0; c < 4; c++) accS[j][c] = 0.f;

        #pragma unroll
        for (int ks = 0; ks < 4; ks++){
            #pragma unroll
            for (int jj = 0; jj < 4; jj++){
                uint32_t rb = (uint32_t)(jj*16)*AT_STRIDE + (uint32_t)(ks*32) + boff4;
                uint32_t bh4[4], bl4[4];
                ldm_x4(K_h + rb, bh4[0], bh4[1], bh4[2], bh4[3]);
                ldm_x4(K_l + rb, bl4[0], bl4[1], bl4[2], bl4[3]);
                mma_bf16(accS[2*jj],   qhf[ks], bh4 + 0);
                mma_bf16(accS[2*jj],   qhf[ks], bl4 + 0);
                mma_bf16(accS[2*jj],   qlf[ks], bh4 + 0);
                mma_bf16(accS[2*jj+1], qhf[ks], bh4 + 2);
                mma_bf16(accS[2*jj+1], qhf[ks], bl4 + 2);
                mma_bf16(accS[2*jj+1], qlf[ks], bh4 + 2);
            }
        }

        const bool diag = (kt == qt);
        const int k0 = kt * 64;
        #pragma unroll
        for (int j = 0; j < 8; j++){
            #pragma unroll
            for (int c = 0; c < 4; c++){
                float sv = accS[j][c] * 0.125f;
                if (diag){
                    int col = k0 + j*8 + tig*2 + (c & 1);
                    int row = (c < 2) ? row0 : row1;
                    if (col > row) sv = -1e30f;
                }
                accS[j][c] = sv;
            }
        }

        #pragma unroll
        for (int half = 0; half < 2; half++){
            float mloc = -1e30f;
            #pragma unroll
            for (int j = 0; j < 8; j++){
                mloc = fmaxf(mloc, accS[j][half*2]);
                mloc = fmaxf(mloc, accS[j][half*2+1]);
            }
            mloc = fmaxf(mloc, __shfl_xor_sync(0xFFFFFFFFu, mloc, 1));
            mloc = fmaxf(mloc, __shfl_xor_sync(0xFFFFFFFFu, mloc, 2));
            const float mnew = fmaxf(m_run[half], mloc);
            const float alpha = __expf(m_run[half] - mnew);
            m_run[half] = mnew;
            float psum = 0.f;
            #pragma unroll
            for (int j = 0; j < 8; j++){
                float p0 = __expf(accS[j][half*2]   - mnew);
                float p1 = __expf(accS[j][half*2+1] - mnew);
                accS[j][half*2]   = p0;
                accS[j][half*2+1] = p1;
                psum += p0 + p1;
            }
            psum += __shfl_xor_sync(0xFFFFFFFFu, psum, 1);
            psum += __shfl_xor_sync(0xFFFFFFFFu, psum, 2);
            l_run[half] = l_run[half]*alpha + psum;
            #pragma unroll
            for (int j = 0; j < 8; j++){
                accO[j][half*2]   *= alpha;
                accO[j][half*2+1] *= alpha;
            }
        }

        #pragma unroll
        for (int ks = 0; ks < 4; ks++){
            uint32_t aPh[4], aPl[4];
            #pragma unroll
            for (int t = 0; t < 4; t++){
                const int j = 2*ks + (t >> 1);
                const int c0 = (t & 1)*2;
                aPh[t] = split_pack(accS[j][c0], accS[j][c0+1], aPl[t]);
            }
            #pragma unroll
            for (int jj = 0; jj < 4; jj++){
                uint32_t rv = (uint32_t)(ks*16)*AT_STRIDE + (uint32_t)(jj*32) + voff4;
                uint32_t vh4[4], vl4[4];
                ldm_x4_t(V_h + rv, vh4[0], vh4[1], vh4[2], vh4[3]);
                ldm_x4_t(V_l + rv, vl4[0], vl4[1], vl4[2], vl4[3]);
                mma_bf16(accO[2*jj],   aPh, vh4 + 0);
                mma_bf16(accO[2*jj],   aPh, vl4 + 0);
                mma_bf16(accO[2*jj],   aPl, vh4 + 0);
                mma_bf16(accO[2*jj+1], aPh, vh4 + 2);
                mma_bf16(accO[2*jj+1], aPh, vl4 + 2);
                mma_bf16(accO[2*jj+1], aPl, vh4 + 2);
            }
        }
    }

    const float rl0 = 1.0f / l_run[0];
    const float rl1 = 1.0f / l_run[1];
    #pragma unroll
    for (int j = 0; j < 8; j++){
        const int col = h*64 + j*8 + tig*2;
        const size_t o0 = (rowb + row0)*Dc + col;
        const size_t o1 = (rowb + row1)*Dc + col;
        uint32_t lo, hi;
        hi = split_pack(accO[j][0]*rl0, accO[j][1]*rl0, lo);
        *(uint32_t*)(aoh + o0) = hi; *(uint32_t*)(aol + o0) = lo;
        hi = split_pack(accO[j][2]*rl1, accO[j][3]*rl1, lo);
        *(uint32_t*)(aoh + o1) = hi; *(uint32_t*)(aol + o1) = lo;
    }
}

// ---------------------------------------------------------------------------
// Fused weight prep (one launch, all layers/matrices)
// ---------------------------------------------------------------------------
#define TSB_PER_LAYER 6912

__global__ void __launch_bounds__(256) transpose_split_all(
    const float* __restrict__ Wq, const float* __restrict__ Wk,
    const float* __restrict__ Wv, const float* __restrict__ Wo,
    const float* __restrict__ W1, const float* __restrict__ W2,
    __nv_bfloat16* __restrict__ gh_, __nv_bfloat16* __restrict__ gl_)
{
    const size_t DD = (size_t)Dc*Dc, DF = (size_t)Dc*Fc;
    int l = blockIdx.x / TSB_PER_LAYER;
    int r = blockIdx.x - l*TSB_PER_LAYER;

    const float* src; size_t dst; int K, N, bx, by;
    if (r < 2304){
        int m = r / 576, t = r - m*576;
        const float* Ws[4] = {Wq, Wk, Wv, Wo};
        src = Ws[m] + (size_t)l*DD; dst = (size_t)l*WT_PER_LAYER + (size_t)m*DD;
        K = Dc; N = Dc; by = t / 24; bx = t - by*24;
    } else if (r < 4608){
        int t = r - 2304;
        src = W1 + (size_t)l*DF; dst = (size_t)l*WT_PER_LAYER + 4*DD;
        K = Dc; N = Fc; by = t / 96; bx = t - by*96;
    } else {
        int t = r - 4608;
        src = W2 + (size_t)l*DF; dst = (size_t)l*WT_PER_LAYER + 4*DD + DF;
        K = Fc; N = Dc; by = t / 24; bx = t - by*24;
    }

    __shared__ float t[32][33];
    const int kb = by*32, nb = bx*32;
    const int x = threadIdx.x & 31, y = (threadIdx.x >> 5) * 4;
    #pragma unroll
    for (int i = 0; i < 4; i++)
        t[y+i][x] = src[(size_t)(kb + y + i)*N + nb + x];
    __syncthreads();
    #pragma unroll
    for (int i = 0; i < 4; i++){
        float v = t[x][y+i];
        __nv_bfloat16 h = __float2bfloat16(v);
        float lo = v - __bfloat162float(h);
        gh_[dst + (size_t)(nb + y + i)*K + kb + x] = h;
        gl_[dst + (size_t)(nb + y + i)*K + kb + x] = __float2bfloat16(lo);
    }
}

// ---------------------------------------------------------------------------
// Activation bf16 split — initial x only
// ---------------------------------------------------------------------------
__global__ void __launch_bounds__(256) split_act(
    const float* __restrict__ in, __nv_bfloat16* __restrict__ oh,
    __nv_bfloat16* __restrict__ ol, int n)
{
    int i = blockIdx.x * 1024 + threadIdx.x * 4;
    if (i >= n) return;
    float4 v = *(const float4*)(in + i);
    float vv[4] = {v.x, v.y, v.z, v.w};
    __nv_bfloat16 h[4], l[4];
    #pragma unroll
    for (int j = 0; j < 4; j++){
        h[j] = __float2bfloat16(vv[j]);
        l[j] = __float2bfloat16(vv[j] - __bfloat162float(h[j]));
    }
    *(uint2*)(oh + i) = *(uint2*)h;
    *(uint2*)(ol + i) = *(uint2*)l;
}

// ---------------------------------------------------------------------------
// out = LayerNorm(res + y) * g + b  -> fp32 out + split bf16
// ---------------------------------------------------------------------------
__global__ void __launch_bounds__(256) add_ln(
    const float* __restrict__ res, const float* __restrict__ y,
    const float* __restrict__ gw, const float* __restrict__ bw,
    float* __restrict__ out,
    __nv_bfloat16* __restrict__ oh, __nv_bfloat16* __restrict__ ol)
{
    const int row = blockIdx.x;
    const float* r  = res + (size_t)row * Dc;
    const float* yy = y   + (size_t)row * Dc;
    float v[3];
    float s = 0.f, s2 = 0.f;
    #pragma unroll
    for (int qq = 0; qq < 3; qq++) {
        int idx = threadIdx.x + qq*256;
        float t = r[idx] + yy[idx];
        v[qq] = t; s += t; s2 += t*t;
    }
    #pragma unroll
    for (int off = 16; off; off >>= 1) {
        s  += __shfl_xor_sync(0xFFFFFFFFu, s,  off);
        s2 += __shfl_xor_sync(0xFFFFFFFFu, s2, off);
    }
    __shared__ float sh[2][8];
    const int w = threadIdx.x >> 5, lane = threadIdx.x & 31;
    if (lane == 0) { sh[0][w] = s; sh[1][w] = s2; }
    __syncthreads();
    float ts = 0.f, ts2 = 0.f;
    #pragma unroll
    for (int i = 0; i < 8; i++) { ts += sh[0][i]; ts2 += sh[1][i]; }
    const float mu  = ts  * (1.0f/768.0f);
    const float var = ts2 * (1.0f/768.0f) - mu*mu;
    const float rstd = rsqrtf(var + 1e-5f);
    #pragma unroll
    for (int qq = 0; qq < 3; qq++) {
        int idx = threadIdx.x + qq*256;
        float o = (v[qq] - mu) * rstd * gw[idx] + bw[idx];
        const size_t off = (size_t)row*Dc + idx;
        out[off] = o;
        __nv_bfloat16 hh = __float2bfloat16(o);
        oh[off] = hh;
        ol[off] = __float2bfloat16(o - __bfloat162float(hh));
    }
}

// ---------------------------------------------------------------------------
// Host launcher
// ---------------------------------------------------------------------------
extern "C" void kernel_launch(void* const* d_in, const int* in_sizes, int n_in,
                              void* d_out, int out_size)
{
    const float* x    = (const float*)d_in[0];
    const float* Wq   = (const float*)d_in[2];
    const float* Wk   = (const float*)d_in[3];
    const float* Wv   = (const float*)d_in[4];
    const float* Wo   = (const float*)d_in[5];
    const float* bo   = (const float*)d_in[6];
    const float* ln1g = (const float*)d_in[7];
    const float* ln1b = (const float*)d_in[8];
    const float* W1   = (const float*)d_in[9];
    const float* b1   = (const float*)d_in[10];
    const float* W2   = (const float*)d_in[11];
    const float* b2   = (const float*)d_in[12];
    const float* ln2g = (const float*)d_in[13];
    const float* ln2b = (const float*)d_in[14];

    float *gx, *gproj, *gh, *gf2;
    __nv_bfloat16 *acth, *actl, *qkvh, *qkvl, *f1h, *f1l, *wh, *wl;
    cudaGetSymbolAddress((void**)&gx,    g_x);
    cudaGetSymbolAddress((void**)&gproj, g_proj);
    cudaGetSymbolAddress((void**)&gh,    g_h);
    cudaGetSymbolAddress((void**)&gf2,   g_f2);
    cudaGetSymbolAddress((void**)&acth,  g_acth);
    cudaGetSymbolAddress((void**)&actl,  g_actl);
    cudaGetSymbolAddress((void**)&qkvh,  g_qkvh);
    cudaGetSymbolAddress((void**)&qkvl,  g_qkvl);
    cudaGetSymbolAddress((void**)&f1h,   g_f1h);
    cudaGetSymbolAddress((void**)&f1l,   g_f1l);
    cudaGetSymbolAddress((void**)&wh,    g_wt_hi);
    cudaGetSymbolAddress((void**)&wl,    g_wt_lo);

    cudaFuncSetAttribute(gemm_tc_t<4>,   cudaFuncAttributeMaxDynamicSharedMemorySize, GSM4);
    cudaFuncSetAttribute(gemm_tc_t<2>,   cudaFuncAttributeMaxDynamicSharedMemorySize, GSM2);
    cudaFuncSetAttribute(flash_attn_mma, cudaFuncAttributeMaxDynamicSharedMemorySize, FA2_SMEM);

    const size_t DD = (size_t)Dc*Dc, DF = (size_t)Dc*Fc;

    transpose_split_all<<<TSB_PER_LAYER*Lc, 256>>>(Wq, Wk, Wv, Wo, W1, W2, wh, wl);

    cudaMemcpyAsync(gx, x, (size_t)Mc*Dc*sizeof(float), cudaMemcpyDeviceToDevice);
    split_act<<<(Mc*Dc)/1024, 256>>>(gx, acth, actl, Mc*Dc);

    const dim3 gQKV(QKVc/128, Mc/128);   // (18, 64)  BM=128
    const dim3 gD64(Dc/128,  Mc/64);     // (6, 128)  BM=64
    const dim3 gF(Fc/128,    Mc/128);    // (24, 64)  BM=128

    for (int l = 0; l < Lc; l++){
        size_t wb = (size_t)l * WT_PER_LAYER;
        const __nv_bfloat16 *qkvw_h = wh+wb,      *qkvw_l = wl+wb;
        const __nv_bfloat16 *ohw = wh+wb+3*DD,    *olw = wl+wb+3*DD;
        const __nv_bfloat16 *w1h = wh+wb+4*DD,    *w1l = wl+wb+4*DD;
        const __nv_bfloat16 *w2h = wh+wb+4*DD+DF, *w2l = wl+wb+4*DD+DF;

        gemm_tc_t<4><<<gQKV, 256, GSM4>>>(acth, actl, qkvw_h, qkvw_l, nullptr,
                                          nullptr, qkvh, qkvl, Mc, QKVc, Dc, QKVc, 0);
        flash_attn_mma<<<dim3(Sc/64, Bc*Hc), 128, FA2_SMEM>>>(qkvh, qkvl, acth, actl);
        gemm_tc_t<2><<<gD64, 256, GSM2>>>(acth, actl, ohw, olw, bo + (size_t)l*Dc,
                                          gproj, nullptr, nullptr, Mc, Dc, Dc, Dc, 0);
        add_ln<<<Mc, 256>>>(gx, gproj, ln1g + (size_t)l*Dc, ln1b + (size_t)l*Dc,
                            gh, acth, actl);
        gemm_tc_t<4><<<gF, 256, GSM4>>>(acth, actl, w1h, w1l, b1 + (size_t)l*Fc,
                                        nullptr, f1h, f1l, Mc, Fc, Dc, Fc, 1);
        gemm_tc_t<2><<<gD64, 256, GSM2>>>(f1h, f1l, w2h, w2l, b2 + (size_t)l*Dc,
                                          gf2, nullptr, nullptr, Mc, Dc, Fc, Dc, 0);
        add_ln<<<Mc, 256>>>(gh, gf2, ln2g + (size_t)l*Dc, ln2b + (size_t)l*Dc,
                            gx, acth, actl);
    }

    cudaMemcpyAsync(d_out, gx, (size_t)Mc*Dc*sizeof(float), cudaMemcpyDeviceToDevice);
}

// round 14
// speedup vs baseline: 1.0396x; 1.0396x over previous
#include <cuda_runtime.h>
#include <cuda_bf16.h>
#include <math.h>
#include <stdint.h>

// Problem constants
#define Bc 4
#define Sc 2048
#define Dc 768
#define Hc 12
#define DHc 64
#define Fc 3072
#define Lc 4
#define Mc (Bc*Sc)   // 8192 rows
#define QKVc 2304    // 3*Dc

// ---------------------------------------------------------------------------
// Scratch (device globals; no allocation allowed)
// ---------------------------------------------------------------------------
__device__ float g_x[(size_t)Mc*Dc];
__device__ float g_proj[2*(size_t)Mc*Dc];   // 2 split-K partials
__device__ float g_h[(size_t)Mc*Dc];
__device__ float g_f2[2*(size_t)Mc*Dc];     // 2 split-K partials

__device__ __nv_bfloat16 g_acth[(size_t)Mc*Dc];
__device__ __nv_bfloat16 g_actl[(size_t)Mc*Dc];
__device__ __nv_bfloat16 g_qkvh[(size_t)Mc*QKVc];
__device__ __nv_bfloat16 g_qkvl[(size_t)Mc*QKVc];
__device__ __nv_bfloat16 g_f1h[(size_t)Mc*Fc];
__device__ __nv_bfloat16 g_f1l[(size_t)Mc*Fc];

#define WT_PER_LAYER ((size_t)4*Dc*Dc + 2*(size_t)Dc*Fc)
__device__ __nv_bfloat16 g_wt_hi[WT_PER_LAYER*Lc];
__device__ __nv_bfloat16 g_wt_lo[WT_PER_LAYER*Lc];

// ---------------------------------------------------------------------------
// Helpers
// ---------------------------------------------------------------------------
__device__ __forceinline__ uint32_t smem_u32(const void* p){
    uint32_t a;
    asm("{ .reg .u64 t; cvta.to.shared.u64 t, %1; cvt.u32.u64 %0, t; }":"=r"(a):"l"(p));
    return a;
}
__device__ __forceinline__ void cpasync16(uint32_t dst, const void* src){
    asm volatile("cp.async.cg.shared.global [%0], [%1], 16;" :: "r"(dst), "l"(src));
}
#define CP_COMMIT() asm volatile("cp.async.commit_group;" ::: "memory")

__device__ __forceinline__ void ldm_x4(uint32_t addr, uint32_t& r0, uint32_t& r1,
                                       uint32_t& r2, uint32_t& r3){
    asm volatile("ldmatrix.sync.aligned.m8n8.x4.shared.b16 {%0,%1,%2,%3}, [%4];"
        : "=r"(r0),"=r"(r1),"=r"(r2),"=r"(r3) : "r"(addr));
}
__device__ __forceinline__ void ldm_x2(uint32_t addr, uint32_t& r0, uint32_t& r1){
    asm volatile("ldmatrix.sync.aligned.m8n8.x2.shared.b16 {%0,%1}, [%2];"
        : "=r"(r0),"=r"(r1) : "r"(addr));
}
__device__ __forceinline__ void ldm_x4_t(uint32_t addr, uint32_t& r0, uint32_t& r1,
                                         uint32_t& r2, uint32_t& r3){
    asm volatile("ldmatrix.sync.aligned.m8n8.x4.trans.shared.b16 {%0,%1,%2,%3}, [%4];"
        : "=r"(r0),"=r"(r1),"=r"(r2),"=r"(r3) : "r"(addr));
}
__device__ __forceinline__ void mma_bf16(float* c, const uint32_t* a, const uint32_t* b){
    asm volatile("mma.sync.aligned.m16n8k16.row.col.f32.bf16.bf16.f32 "
        "{%0,%1,%2,%3}, {%4,%5,%6,%7}, {%8,%9}, {%0,%1,%2,%3};"
        : "+f"(c[0]),"+f"(c[1]),"+f"(c[2]),"+f"(c[3])
        : "r"(a[0]),"r"(a[1]),"r"(a[2]),"r"(a[3]), "r"(b[0]),"r"(b[1]));
}
__device__ __forceinline__ uint32_t pack_bf2(__nv_bfloat16 a, __nv_bfloat16 b){
    union { __nv_bfloat162 v; uint32_t u; } t;
    t.v.x = a; t.v.y = b; return t.u;
}
__device__ __forceinline__ uint32_t split_pack(float v0, float v1, uint32_t& lo){
    __nv_bfloat16 h0 = __float2bfloat16(v0);
    __nv_bfloat16 h1 = __float2bfloat16(v1);
    lo = pack_bf2(__float2bfloat16(v0 - __bfloat162float(h0)),
                  __float2bfloat16(v1 - __bfloat162float(h1)));
    return pack_bf2(h0, h1);
}

// ---------------------------------------------------------------------------
// mma.sync GEMM (3-term bf16 split), BM=128 x BN=128 x BK=32, 2 CTAs/SM.
// Optional split-K via blockIdx.z (ksplit): partial z writes Cf + z*Mc*ldc.
// ---------------------------------------------------------------------------
#define T_STRIDE 80
#define TILE_B   (128*T_STRIDE)
#define STAGE_B  (4*TILE_B)
#define GSM_TOTAL (2*STAGE_B)    // 80 KB -> 2 CTAs/SM

__global__ void __launch_bounds__(256, 2) gemm_tc(
    const __nv_bfloat16* __restrict__ Ah, const __nv_bfloat16* __restrict__ Al,
    const __nv_bfloat16* __restrict__ Bh, const __nv_bfloat16* __restrict__ Bl,
    const float* __restrict__ bias,
    float* __restrict__ Cf,
    __nv_bfloat16* __restrict__ Ch, __nv_bfloat16* __restrict__ Cl,
    int M, int N, int K, int ldc, int epi, int ksplit)
{
    extern __shared__ char smem[];
    const uint32_t sbase = smem_u32(smem);
    const int tid = threadIdx.x;
    const int wid = tid >> 5, lane = tid & 31;
    const int warpM = wid >> 2, warpN = wid & 3;
    const int m0 = blockIdx.y * 128, n0 = blockIdx.x * 128;
    const int kz = blockIdx.z;
    const int ksl = K / ksplit;
    const int kbase = kz * ksl;

    const __nv_bfloat16* srcs[4] = {Ah, Al, Bh, Bl};
    const int rowbase[4] = {m0, m0, n0, n0};

    auto load_chunk = [&](int c, int s){
        const int k0 = kbase + c * 32;
        #pragma unroll
        for (int i = 0; i < 8; i++){
            int idx = tid + i*256;
            int seg  = idx & 3;
            int row  = (idx >> 2) & 127;
            int t    = idx >> 9;
            uint32_t dst = sbase + s*STAGE_B + t*TILE_B + row*T_STRIDE + seg*16;
            const char* src = (const char*)(srcs[t] + (size_t)(rowbase[t] + row)*K + k0) + seg*16;
            cpasync16(dst, src);
        }
        CP_COMMIT();
    };

    float acc[4][4][4];
    #pragma unroll
    for (int i = 0; i < 4; i++)
        #pragma unroll
        for (int j = 0; j < 4; j++)
            #pragma unroll
            for (int r = 0; r < 4; r++) acc[i][j][r] = 0.f;

    const int NC = ksl / 32;
    load_chunk(0, 0);

    const uint32_t aoff = (uint32_t)(lane & 15) * T_STRIDE + (uint32_t)(lane >> 4) * 16;
    const uint32_t boff = (uint32_t)(lane & 7)  * T_STRIDE + (uint32_t)((lane >> 3) & 1) * 16;

    for (int c = 0; c < NC; c++){
        const int s = c & 1;
        if (c + 1 < NC){ load_chunk(c + 1, s ^ 1); }
        if (c + 1 < NC) asm volatile("cp.async.wait_group 1;" ::: "memory");
        else            asm volatile("cp.async.wait_group 0;" ::: "memory");
        __syncthreads();

        const uint32_t st  = sbase + s*STAGE_B;
        const uint32_t A_h = st,            A_l = st + TILE_B;
        const uint32_t B_h = st + 2*TILE_B, B_l = st + 3*TILE_B;

        #pragma unroll
        for (int ks = 0; ks < 2; ks++){
            uint32_t bh[4][2], bl[4][2];
            #pragma unroll
            for (int j = 0; j < 4; j++){
                uint32_t rb = (uint32_t)(warpN*32 + j*8) * T_STRIDE + (uint32_t)(ks*32) + boff;
                ldm_x2(B_h + rb, bh[j][0], bh[j][1]);
                ldm_x2(B_l + rb, bl[j][0], bl[j][1]);
            }
            #pragma unroll
            for (int i = 0; i < 4; i++){
                uint32_t ah4[4], al4[4];
                uint32_t ra = (uint32_t)(warpM*64 + i*16) * T_STRIDE + (uint32_t)(ks*32) + aoff;
                ldm_x4(A_h + ra, ah4[0], ah4[1], ah4[2], ah4[3]);
                ldm_x4(A_l + ra, al4[0], al4[1], al4[2], al4[3]);
                #pragma unroll
                for (int j = 0; j < 4; j++){
                    mma_bf16(acc[i][j], ah4, bh[j]);
                    mma_bf16(acc[i][j], ah4, bl[j]);
                    mma_bf16(acc[i][j], al4, bh[j]);
                }
            }
        }
        __syncthreads();
    }

    const int gid = lane >> 2, tig = lane & 3;
    float* Cfz = Cf ? (Cf + (size_t)kz * (size_t)Mc * (size_t)ldc) : Cf;
    const bool addb = (bias != nullptr) && (kz == 0);
    #pragma unroll
    for (int i = 0; i < 4; i++){
        #pragma unroll
        for (int j = 0; j < 4; j++){
            const int col = n0 + warpN*32 + j*8 + tig*2;
            float b0 = addb ? bias[col]     : 0.f;
            float b1 = addb ? bias[col + 1] : 0.f;
            #pragma unroll
            for (int half = 0; half < 2; half++){
                const int row = m0 + warpM*64 + i*16 + gid + half*8;
                float v0 = acc[i][j][half*2 + 0] + b0;
                float v1 = acc[i][j][half*2 + 1] + b1;
                if (epi){
                    v0 = 0.5f * v0 * (1.0f + erff(v0 * 0.70710678118654752f));
                    v1 = 0.5f * v1 * (1.0f + erff(v1 * 0.70710678118654752f));
                }
                const size_t off = (size_t)row * ldc + col;
                if (Cfz) *(float2*)(Cfz + off) = make_float2(v0, v1);
                if (Ch){
                    uint32_t lo, hi = split_pack(v0, v1, lo);
                    *(uint32_t*)(Ch + off) = hi;
                    *(uint32_t*)(Cl + off) = lo;
                }
            }
        }
    }
}

// ---------------------------------------------------------------------------
// Flash attention via mma.sync (causal) — unchanged from R12
// ---------------------------------------------------------------------------
#define AT_STRIDE 144
#define KV_STAGE  36864
#define FQ_H      36864
#define FQ_L      46080
#define FA2_SMEM  73728

__global__ void __launch_bounds__(128) flash_attn_mma(
    const __nv_bfloat16* __restrict__ qkvh, const __nv_bfloat16* __restrict__ qkvl,
    __nv_bfloat16* __restrict__ aoh, __nv_bfloat16* __restrict__ aol)
{
    extern __shared__ char smem[];
    const uint32_t sbase = smem_u32(smem);
    const int tid = threadIdx.x;
    const int wid = tid >> 5, lane = tid & 31;
    const int gid = lane >> 2, tig = lane & 3;
    const int bh = blockIdx.y;
    const int b = bh / Hc, h = bh - b*Hc;
    const int qt = (int)gridDim.x - 1 - (int)blockIdx.x;
    const int q0 = qt * 64;
    const size_t rowb = (size_t)b * Sc;
    const int qcol = h*64, kcol = Dc + h*64, vcol = 2*Dc + h*64;

    auto load_kv = [&](int kt, int s){
        const int k0 = kt * 64;
        const __nv_bfloat16* srcs[4] = {qkvh, qkvl, qkvh, qkvl};
        const int cols[4] = {kcol, kcol, vcol, vcol};
        #pragma unroll
        for (int i = 0; i < 16; i++){
            int idx = tid + i*128;
            int arr = idx >> 9;
            int rem = idx & 511;
            int row = rem >> 3, ch = rem & 7;
            const char* src = (const char*)(srcs[arr] + (rowb + k0 + row)*QKVc + cols[arr]) + ch*16;
            cpasync16(sbase + s*KV_STAGE + arr*9216 + row*AT_STRIDE + ch*16, src);
        }
        CP_COMMIT();
    };

    {
        #pragma unroll
        for (int i = 0; i < 8; i++){
            int idx = tid + i*128;
            int arr = idx >> 9;
            int rem = idx & 511;
            int row = rem >> 3, ch = rem & 7;
            const __nv_bfloat16* sp = arr ? qkvl : qkvh;
            const char* src = (const char*)(sp + (rowb + q0 + row)*QKVc + qcol) + ch*16;
            cpasync16(sbase + (arr ? FQ_L : FQ_H) + row*AT_STRIDE + ch*16, src);
        }
        load_kv(0, 0);
    }
    asm volatile("cp.async.wait_group 0;" ::: "memory");
    __syncthreads();

    uint32_t qhf[4][4], qlf[4][4];
    {
        const uint32_t ao_ = (uint32_t)(lane & 15)*AT_STRIDE + (uint32_t)(lane >> 4)*16;
        #pragma unroll
        for (int ks = 0; ks < 4; ks++){
            uint32_t ra = (uint32_t)(wid*16)*AT_STRIDE + (uint32_t)(ks*32) + ao_;
            ldm_x4(sbase + FQ_H + ra, qhf[ks][0], qhf[ks][1], qhf[ks][2], qhf[ks][3]);
            ldm_x4(sbase + FQ_L + ra, qlf[ks][0], qlf[ks][1], qlf[ks][2], qlf[ks][3]);
        }
    }
    __syncthreads();

    float accO[8][4];
    #pragma unroll
    for (int j = 0; j < 8; j++)
        #pragma unroll
        for (int c = 0; c < 4; c++) accO[j][c] = 0.f;
    float m_run[2] = {-1e30f, -1e30f};
    float l_run[2] = {0.f, 0.f};

    const uint32_t boff4 = (uint32_t)((lane & 7) + ((lane >> 4) << 3))*AT_STRIDE
                         + (uint32_t)((lane >> 3) & 1)*16;
    const uint32_t voff4 = (uint32_t)(lane & 15)*AT_STRIDE + (uint32_t)(lane >> 4)*16;

    const int row0 = q0 + wid*16 + gid;
    const int row1 = row0 + 8;

    for (int kt = 0; kt <= qt; kt++){
        const int s = kt & 1;
        if (kt > 0){
            asm volatile("cp.async.wait_group 0;" ::: "memory");
            __syncthreads();
        }
        if (kt < qt) load_kv(kt + 1, s ^ 1);

        const uint32_t K_h = sbase + s*KV_STAGE;
        const uint32_t K_l = K_h + 9216;
        const uint32_t V_h = K_h + 18432;
        const uint32_t V_l = K_h + 27648;

        float accS[8][4];
        #pragma unroll
        for (int j = 0; j < 8; j++)
            #pragma unroll
            for (int c = 0; c < 4; c++) accS[j][c] = 0.f;

        #pragma unroll
        for (int ks = 0; ks < 4; ks++){
            #pragma unroll
            for (int jj = 0; jj < 4; jj++){
                uint32_t rb = (uint32_t)(jj*16)*AT_STRIDE + (uint32_t)(ks*32) + boff4;
                uint32_t bh4[4], bl4[4];
                ldm_x4(K_h + rb, bh4[0], bh4[1], bh4[2], bh4[3]);
                ldm_x4(K_l + rb, bl4[0], bl4[1], bl4[2], bl4[3]);
                mma_bf16(accS[2*jj],   qhf[ks], bh4 + 0);
                mma_bf16(accS[2*jj],   qhf[ks], bl4 + 0);
                mma_bf16(accS[2*jj],   qlf[ks], bh4 + 0);
                mma_bf16(accS[2*jj+1], qhf[ks], bh4 + 2);
                mma_bf16(accS[2*jj+1], qhf[ks], bl4 + 2);
                mma_bf16(accS[2*jj+1], qlf[ks], bh4 + 2);
            }
        }

        const bool diag = (kt == qt);
        const int k0 = kt * 64;
        #pragma unroll
        for (int j = 0; j < 8; j++){
            #pragma unroll
            for (int c = 0; c < 4; c++){
                float sv = accS[j][c] * 0.125f;
                if (diag){
                    int col = k0 + j*8 + tig*2 + (c & 1);
                    int row = (c < 2) ? row0 : row1;
                    if (col > row) sv = -1e30f;
                }
                accS[j][c] = sv;
            }
        }

        #pragma unroll
        for (int half = 0; half < 2; half++){
            float mloc = -1e30f;
            #pragma unroll
            for (int j = 0; j < 8; j++){
                mloc = fmaxf(mloc, accS[j][half*2]);
                mloc = fmaxf(mloc, accS[j][half*2+1]);
            }
            mloc = fmaxf(mloc, __shfl_xor_sync(0xFFFFFFFFu, mloc, 1));
            mloc = fmaxf(mloc, __shfl_xor_sync(0xFFFFFFFFu, mloc, 2));
            const float mnew = fmaxf(m_run[half], mloc);
            const float alpha = __expf(m_run[half] - mnew);
            m_run[half] = mnew;
            float psum = 0.f;
            #pragma unroll
            for (int j = 0; j < 8; j++){
                float p0 = __expf(accS[j][half*2]   - mnew);
                float p1 = __expf(accS[j][half*2+1] - mnew);
                accS[j][half*2]   = p0;
                accS[j][half*2+1] = p1;
                psum += p0 + p1;
            }
            psum += __shfl_xor_sync(0xFFFFFFFFu, psum, 1);
            psum += __shfl_xor_sync(0xFFFFFFFFu, psum, 2);
            l_run[half] = l_run[half]*alpha + psum;
            #pragma unroll
            for (int j = 0; j < 8; j++){
                accO[j][half*2]   *= alpha;
                accO[j][half*2+1] *= alpha;
            }
        }

        #pragma unroll
        for (int ks = 0; ks < 4; ks++){
            uint32_t aPh[4], aPl[4];
            #pragma unroll
            for (int t = 0; t < 4; t++){
                const int j = 2*ks + (t >> 1);
                const int c0 = (t & 1)*2;
                aPh[t] = split_pack(accS[j][c0], accS[j][c0+1], aPl[t]);
            }
            #pragma unroll
            for (int jj = 0; jj < 4; jj++){
                uint32_t rv = (uint32_t)(ks*16)*AT_STRIDE + (uint32_t)(jj*32) + voff4;
                uint32_t vh4[4], vl4[4];
                ldm_x4_t(V_h + rv, vh4[0], vh4[1], vh4[2], vh4[3]);
                ldm_x4_t(V_l + rv, vl4[0], vl4[1], vl4[2], vl4[3]);
                mma_bf16(accO[2*jj],   aPh, vh4 + 0);
                mma_bf16(accO[2*jj],   aPh, vl4 + 0);
                mma_bf16(accO[2*jj],   aPl, vh4 + 0);
                mma_bf16(accO[2*jj+1], aPh, vh4 + 2);
                mma_bf16(accO[2*jj+1], aPh, vl4 + 2);
                mma_bf16(accO[2*jj+1], aPl, vh4 + 2);
            }
        }
    }

    const float rl0 = 1.0f / l_run[0];
    const float rl1 = 1.0f / l_run[1];
    #pragma unroll
    for (int j = 0; j < 8; j++){
        const int col = h*64 + j*8 + tig*2;
        const size_t o0 = (rowb + row0)*Dc + col;
        const size_t o1 = (rowb + row1)*Dc + col;
        uint32_t lo, hi;
        hi = split_pack(accO[j][0]*rl0, accO[j][1]*rl0, lo);
        *(uint32_t*)(aoh + o0) = hi; *(uint32_t*)(aol + o0) = lo;
        hi = split_pack(accO[j][2]*rl1, accO[j][3]*rl1, lo);
        *(uint32_t*)(aoh + o1) = hi; *(uint32_t*)(aol + o1) = lo;
    }
}

// ---------------------------------------------------------------------------
// Fused weight prep (one launch, all layers/matrices)
// ---------------------------------------------------------------------------
#define TSB_PER_LAYER 6912

__global__ void __launch_bounds__(256) transpose_split_all(
    const float* __restrict__ Wq, const float* __restrict__ Wk,
    const float* __restrict__ Wv, const float* __restrict__ Wo,
    const float* __restrict__ W1, const float* __restrict__ W2,
    __nv_bfloat16* __restrict__ gh_, __nv_bfloat16* __restrict__ gl_)
{
    const size_t DD = (size_t)Dc*Dc, DF = (size_t)Dc*Fc;
    int l = blockIdx.x / TSB_PER_LAYER;
    int r = blockIdx.x - l*TSB_PER_LAYER;

    const float* src; size_t dst; int K, N, bx, by;
    if (r < 2304){
        int m = r / 576, t = r - m*576;
        const float* Ws[4] = {Wq, Wk, Wv, Wo};
        src = Ws[m] + (size_t)l*DD; dst = (size_t)l*WT_PER_LAYER + (size_t)m*DD;
        K = Dc; N = Dc; by = t / 24; bx = t - by*24;
    } else if (r < 4608){
        int t = r - 2304;
        src = W1 + (size_t)l*DF; dst = (size_t)l*WT_PER_LAYER + 4*DD;
        K = Dc; N = Fc; by = t / 96; bx = t - by*96;
    } else {
        int t = r - 4608;
        src = W2 + (size_t)l*DF; dst = (size_t)l*WT_PER_LAYER + 4*DD + DF;
        K = Fc; N = Dc; by = t / 24; bx = t - by*24;
    }

    __shared__ float t[32][33];
    const int kb = by*32, nb = bx*32;
    const int x = threadIdx.x & 31, y = (threadIdx.x >> 5) * 4;
    #pragma unroll
    for (int i = 0; i < 4; i++)
        t[y+i][x] = src[(size_t)(kb + y + i)*N + nb + x];
    __syncthreads();
    #pragma unroll
    for (int i = 0; i < 4; i++){
        float v = t[x][y+i];
        __nv_bfloat16 h = __float2bfloat16(v);
        float lo = v - __bfloat162float(h);
        gh_[dst + (size_t)(nb + y + i)*K + kb + x] = h;
        gl_[dst + (size_t)(nb + y + i)*K + kb + x] = __float2bfloat16(lo);
    }
}

// ---------------------------------------------------------------------------
// Activation bf16 split — initial x only
// ---------------------------------------------------------------------------
__global__ void __launch_bounds__(256) split_act(
    const float* __restrict__ in, __nv_bfloat16* __restrict__ oh,
    __nv_bfloat16* __restrict__ ol, int n)
{
    int i = blockIdx.x * 1024 + threadIdx.x * 4;
    if (i >= n) return;
    float4 v = *(const float4*)(in + i);
    float vv[4] = {v.x, v.y, v.z, v.w};
    __nv_bfloat16 h[4], l[4];
    #pragma unroll
    for (int j = 0; j < 4; j++){
        h[j] = __float2bfloat16(vv[j]);
        l[j] = __float2bfloat16(vv[j] - __bfloat162float(h[j]));
    }
    *(uint2*)(oh + i) = *(uint2*)h;
    *(uint2*)(ol + i) = *(uint2*)l;
}

// ---------------------------------------------------------------------------
// out = LayerNorm(res + ya + yb) * g + b  -> fp32 out + split bf16
// (ya, yb are the two split-K partials)
// ---------------------------------------------------------------------------
__global__ void __launch_bounds__(256) add_ln(
    const float* __restrict__ res, const float* __restrict__ ya,
    const float* __restrict__ yb,
    const float* __restrict__ gw, const float* __restrict__ bw,
    float* __restrict__ out,
    __nv_bfloat16* __restrict__ oh, __nv_bfloat16* __restrict__ ol)
{
    const int row = blockIdx.x;
    const float* r  = res + (size_t)row * Dc;
    const float* a  = ya  + (size_t)row * Dc;
    const float* bb = yb  + (size_t)row * Dc;
    float v[3];
    float s = 0.f, s2 = 0.f;
    #pragma unroll
    for (int qq = 0; qq < 3; qq++) {
        int idx = threadIdx.x + qq*256;
        float t = r[idx] + a[idx] + bb[idx];
        v[qq] = t; s += t; s2 += t*t;
    }
    #pragma unroll
    for (int off = 16; off; off >>= 1) {
        s  += __shfl_xor_sync(0xFFFFFFFFu, s,  off);
        s2 += __shfl_xor_sync(0xFFFFFFFFu, s2, off);
    }
    __shared__ float sh[2][8];
    const int w = threadIdx.x >> 5, lane = threadIdx.x & 31;
    if (lane == 0) { sh[0][w] = s; sh[1][w] = s2; }
    __syncthreads();
    float ts = 0.f, ts2 = 0.f;
    #pragma unroll
    for (int i = 0; i < 8; i++) { ts += sh[0][i]; ts2 += sh[1][i]; }
    const float mu  = ts  * (1.0f/768.0f);
    const float var = ts2 * (1.0f/768.0f) - mu*mu;
    const float rstd = rsqrtf(var + 1e-5f);
    #pragma unroll
    for (int qq = 0; qq < 3; qq++) {
        int idx = threadIdx.x + qq*256;
        float o = (v[qq] - mu) * rstd * gw[idx] + bw[idx];
        const size_t off = (size_t)row*Dc + idx;
        out[off] = o;
        __nv_bfloat16 hh = __float2bfloat16(o);
        oh[off] = hh;
        ol[off] = __float2bfloat16(o - __bfloat162float(hh));
    }
}

// ---------------------------------------------------------------------------
// Host launcher
// ---------------------------------------------------------------------------
extern "C" void kernel_launch(void* const* d_in, const int* in_sizes, int n_in,
                              void* d_out, int out_size)
{
    const float* x    = (const float*)d_in[0];
    const float* Wq   = (const float*)d_in[2];
    const float* Wk   = (const float*)d_in[3];
    const float* Wv   = (const float*)d_in[4];
    const float* Wo   = (const float*)d_in[5];
    const float* bo   = (const float*)d_in[6];
    const float* ln1g = (const float*)d_in[7];
    const float* ln1b = (const float*)d_in[8];
    const float* W1   = (const float*)d_in[9];
    const float* b1   = (const float*)d_in[10];
    const float* W2   = (const float*)d_in[11];
    const float* b2   = (const float*)d_in[12];
    const float* ln2g = (const float*)d_in[13];
    const float* ln2b = (const float*)d_in[14];

    float *gx, *gproj, *gh, *gf2;
    __nv_bfloat16 *acth, *actl, *qkvh, *qkvl, *f1h, *f1l, *wh, *wl;
    cudaGetSymbolAddress((void**)&gx,    g_x);
    cudaGetSymbolAddress((void**)&gproj, g_proj);
    cudaGetSymbolAddress((void**)&gh,    g_h);
    cudaGetSymbolAddress((void**)&gf2,   g_f2);
    cudaGetSymbolAddress((void**)&acth,  g_acth);
    cudaGetSymbolAddress((void**)&actl,  g_actl);
    cudaGetSymbolAddress((void**)&qkvh,  g_qkvh);
    cudaGetSymbolAddress((void**)&qkvl,  g_qkvl);
    cudaGetSymbolAddress((void**)&f1h,   g_f1h);
    cudaGetSymbolAddress((void**)&f1l,   g_f1l);
    cudaGetSymbolAddress((void**)&wh,    g_wt_hi);
    cudaGetSymbolAddress((void**)&wl,    g_wt_lo);

    cudaFuncSetAttribute(gemm_tc,        cudaFuncAttributeMaxDynamicSharedMemorySize, GSM_TOTAL);
    cudaFuncSetAttribute(flash_attn_mma, cudaFuncAttributeMaxDynamicSharedMemorySize, FA2_SMEM);

    const size_t DD = (size_t)Dc*Dc, DF = (size_t)Dc*Fc;
    const size_t MD = (size_t)Mc*Dc;

    transpose_split_all<<<TSB_PER_LAYER*Lc, 256>>>(Wq, Wk, Wv, Wo, W1, W2, wh, wl);

    cudaMemcpyAsync(gx, x, MD*sizeof(float), cudaMemcpyDeviceToDevice);
    split_act<<<(Mc*Dc)/1024, 256>>>(gx, acth, actl, Mc*Dc);

    const dim3 gQKV(QKVc/128, Mc/128);      // (18, 64)
    const dim3 gDs(Dc/128, Mc/128, 2);      // (6, 64, 2) split-K=2
    const dim3 gF(Fc/128, Mc/128);          // (24, 64)

    for (int l = 0; l < Lc; l++){
        size_t wb = (size_t)l * WT_PER_LAYER;
        const __nv_bfloat16 *qkvw_h = wh+wb,      *qkvw_l = wl+wb;
        const __nv_bfloat16 *ohw = wh+wb+3*DD,    *olw = wl+wb+3*DD;
        const __nv_bfloat16 *w1h = wh+wb+4*DD,    *w1l = wl+wb+4*DD;
        const __nv_bfloat16 *w2h = wh+wb+4*DD+DF, *w2l = wl+wb+4*DD+DF;

        gemm_tc<<<gQKV, 256, GSM_TOTAL>>>(acth, actl, qkvw_h, qkvw_l, nullptr,
                                          nullptr, qkvh, qkvl, Mc, QKVc, Dc, QKVc, 0, 1);
        flash_attn_mma<<<dim3(Sc/64, Bc*Hc), 128, FA2_SMEM>>>(qkvh, qkvl, acth, actl);
        // Wo: split-K=2 -> two fp32 partials in g_proj
        gemm_tc<<<gDs, 256, GSM_TOTAL>>>(acth, actl, ohw, olw, bo + (size_t)l*Dc,
                                         gproj, nullptr, nullptr, Mc, Dc, Dc, Dc, 0, 2);
        add_ln<<<Mc, 256>>>(gx, gproj, gproj + MD,
                            ln1g + (size_t)l*Dc, ln1b + (size_t)l*Dc, gh, acth, actl);
        gemm_tc<<<gF, 256, GSM_TOTAL>>>(acth, actl, w1h, w1l, b1 + (size_t)l*Fc,
                                        nullptr, f1h, f1l, Mc, Fc, Dc, Fc, 1, 1);
        // W2: split-K=2 -> two fp32 partials in g_f2
        gemm_tc<<<gDs, 256, GSM_TOTAL>>>(f1h, f1l, w2h, w2l, b2 + (size_t)l*Dc,
                                         gf2, nullptr, nullptr, Mc, Dc, Fc, Dc, 0, 2);
        add_ln<<<Mc, 256>>>(gh, gf2, gf2 + MD,
                            ln2g + (size_t)l*Dc, ln2b + (size_t)l*Dc, gx, acth, actl);
    }

    cudaMemcpyAsync(d_out, gx, MD*sizeof(float), cudaMemcpyDeviceToDevice);
}

// round 16
// speedup vs baseline: 1.0531x; 1.0130x over previous
#include <cuda_runtime.h>
#include <cuda_bf16.h>
#include <math.h>
#include <stdint.h>

// Problem constants
#define Bc 4
#define Sc 2048
#define Dc 768
#define Hc 12
#define DHc 64
#define Fc 3072
#define Lc 4
#define Mc (Bc*Sc)   // 8192 rows
#define QKVc 2304    // 3*Dc

// ---------------------------------------------------------------------------
// Scratch (device globals; no allocation allowed)
// ---------------------------------------------------------------------------
__device__ float g_x[(size_t)Mc*Dc];
__device__ float g_proj[2*(size_t)Mc*Dc];   // 2 split-K partials
__device__ float g_h[(size_t)Mc*Dc];
__device__ float g_f2[2*(size_t)Mc*Dc];     // 2 split-K partials

__device__ __nv_bfloat16 g_acth[(size_t)Mc*Dc];
__device__ __nv_bfloat16 g_actl[(size_t)Mc*Dc];
__device__ __nv_bfloat16 g_qkvh[(size_t)Mc*QKVc];
__device__ __nv_bfloat16 g_qkvl[(size_t)Mc*QKVc];
__device__ __nv_bfloat16 g_f1h[(size_t)Mc*Fc];
__device__ __nv_bfloat16 g_f1l[(size_t)Mc*Fc];

#define WT_PER_LAYER ((size_t)4*Dc*Dc + 2*(size_t)Dc*Fc)
__device__ __nv_bfloat16 g_wt_hi[WT_PER_LAYER*Lc];
__device__ __nv_bfloat16 g_wt_lo[WT_PER_LAYER*Lc];

// ---------------------------------------------------------------------------
// Helpers
// ---------------------------------------------------------------------------
__device__ __forceinline__ uint32_t smem_u32(const void* p){
    uint32_t a;
    asm("{ .reg .u64 t; cvta.to.shared.u64 t, %1; cvt.u32.u64 %0, t; }":"=r"(a):"l"(p));
    return a;
}
__device__ __forceinline__ void cpasync16(uint32_t dst, const void* src){
    asm volatile("cp.async.cg.shared.global [%0], [%1], 16;" :: "r"(dst), "l"(src));
}
#define CP_COMMIT() asm volatile("cp.async.commit_group;" ::: "memory")

__device__ __forceinline__ void ldm_x4(uint32_t addr, uint32_t& r0, uint32_t& r1,
                                       uint32_t& r2, uint32_t& r3){
    asm volatile("ldmatrix.sync.aligned.m8n8.x4.shared.b16 {%0,%1,%2,%3}, [%4];"
        : "=r"(r0),"=r"(r1),"=r"(r2),"=r"(r3) : "r"(addr));
}
__device__ __forceinline__ void ldm_x2(uint32_t addr, uint32_t& r0, uint32_t& r1){
    asm volatile("ldmatrix.sync.aligned.m8n8.x2.shared.b16 {%0,%1}, [%2];"
        : "=r"(r0),"=r"(r1) : "r"(addr));
}
__device__ __forceinline__ void ldm_x4_t(uint32_t addr, uint32_t& r0, uint32_t& r1,
                                         uint32_t& r2, uint32_t& r3){
    asm volatile("ldmatrix.sync.aligned.m8n8.x4.trans.shared.b16 {%0,%1,%2,%3}, [%4];"
        : "=r"(r0),"=r"(r1),"=r"(r2),"=r"(r3) : "r"(addr));
}
__device__ __forceinline__ void mma_bf16(float* c, const uint32_t* a, const uint32_t* b){
    asm volatile("mma.sync.aligned.m16n8k16.row.col.f32.bf16.bf16.f32 "
        "{%0,%1,%2,%3}, {%4,%5,%6,%7}, {%8,%9}, {%0,%1,%2,%3};"
        : "+f"(c[0]),"+f"(c[1]),"+f"(c[2]),"+f"(c[3])
        : "r"(a[0]),"r"(a[1]),"r"(a[2]),"r"(a[3]), "r"(b[0]),"r"(b[1]));
}
__device__ __forceinline__ uint32_t pack_bf2(__nv_bfloat16 a, __nv_bfloat16 b){
    union { __nv_bfloat162 v; uint32_t u; } t;
    t.v.x = a; t.v.y = b; return t.u;
}
__device__ __forceinline__ uint32_t split_pack(float v0, float v1, uint32_t& lo){
    __nv_bfloat16 h0 = __float2bfloat16(v0);
    __nv_bfloat16 h1 = __float2bfloat16(v1);
    lo = pack_bf2(__float2bfloat16(v0 - __bfloat162float(h0)),
                  __float2bfloat16(v1 - __bfloat162float(h1)));
    return pack_bf2(h0, h1);
}

// ---------------------------------------------------------------------------
// mma.sync GEMM (3-term bf16 split), BM=128 x BN=128 x BK=32, 2 CTAs/SM.
// Term-major inner loop over i-pairs: HMMA RAW chain distance = 8.
// epi: 0 none, 1 exact GELU, 2 scale q-columns (col<Dc) by 0.125.
// Optional split-K via blockIdx.z (ksplit): partial z writes Cf + z*Mc*ldc.
// ---------------------------------------------------------------------------
#define T_STRIDE 80
#define TILE_B   (128*T_STRIDE)
#define STAGE_B  (4*TILE_B)
#define GSM_TOTAL (2*STAGE_B)    // 80 KB -> 2 CTAs/SM

__global__ void __launch_bounds__(256, 2) gemm_tc(
    const __nv_bfloat16* __restrict__ Ah, const __nv_bfloat16* __restrict__ Al,
    const __nv_bfloat16* __restrict__ Bh, const __nv_bfloat16* __restrict__ Bl,
    const float* __restrict__ bias,
    float* __restrict__ Cf,
    __nv_bfloat16* __restrict__ Ch, __nv_bfloat16* __restrict__ Cl,
    int M, int N, int K, int ldc, int epi, int ksplit)
{
    extern __shared__ char smem[];
    const uint32_t sbase = smem_u32(smem);
    const int tid = threadIdx.x;
    const int wid = tid >> 5, lane = tid & 31;
    const int warpM = wid >> 2, warpN = wid & 3;
    const int m0 = blockIdx.y * 128, n0 = blockIdx.x * 128;
    const int kz = blockIdx.z;
    const int ksl = K / ksplit;
    const int kbase = kz * ksl;

    const __nv_bfloat16* srcs[4] = {Ah, Al, Bh, Bl};
    const int rowbase[4] = {m0, m0, n0, n0};

    auto load_chunk = [&](int c, int s){
        const int k0 = kbase + c * 32;
        #pragma unroll
        for (int i = 0; i < 8; i++){
            int idx = tid + i*256;
            int seg  = idx & 3;
            int row  = (idx >> 2) & 127;
            int t    = idx >> 9;
            uint32_t dst = sbase + s*STAGE_B + t*TILE_B + row*T_STRIDE + seg*16;
            const char* src = (const char*)(srcs[t] + (size_t)(rowbase[t] + row)*K + k0) + seg*16;
            cpasync16(dst, src);
        }
        CP_COMMIT();
    };

    float acc[4][4][4];
    #pragma unroll
    for (int i = 0; i < 4; i++)
        #pragma unroll
        for (int j = 0; j < 4; j++)
            #pragma unroll
            for (int r = 0; r < 4; r++) acc[i][j][r] = 0.f;

    const int NC = ksl / 32;
    load_chunk(0, 0);

    const uint32_t aoff = (uint32_t)(lane & 15) * T_STRIDE + (uint32_t)(lane >> 4) * 16;
    const uint32_t boff = (uint32_t)(lane & 7)  * T_STRIDE + (uint32_t)((lane >> 3) & 1) * 16;

    for (int c = 0; c < NC; c++){
        const int s = c & 1;
        if (c + 1 < NC){ load_chunk(c + 1, s ^ 1); }
        if (c + 1 < NC) asm volatile("cp.async.wait_group 1;" ::: "memory");
        else            asm volatile("cp.async.wait_group 0;" ::: "memory");
        __syncthreads();

        const uint32_t st  = sbase + s*STAGE_B;
        const uint32_t A_h = st,            A_l = st + TILE_B;
        const uint32_t B_h = st + 2*TILE_B, B_l = st + 3*TILE_B;

        #pragma unroll
        for (int ks = 0; ks < 2; ks++){
            uint32_t bh[4][2], bl[4][2];
            #pragma unroll
            for (int j = 0; j < 4; j++){
                uint32_t rb = (uint32_t)(warpN*32 + j*8) * T_STRIDE + (uint32_t)(ks*32) + boff;
                ldm_x2(B_h + rb, bh[j][0], bh[j][1]);
                ldm_x2(B_l + rb, bl[j][0], bl[j][1]);
            }
            #pragma unroll
            for (int ip = 0; ip < 2; ip++){
                // load A fragments for i-pair (ip*2, ip*2+1)
                uint32_t ah4[2][4], al4[2][4];
                #pragma unroll
                for (int ii = 0; ii < 2; ii++){
                    const int i = ip*2 + ii;
                    uint32_t ra = (uint32_t)(warpM*64 + i*16) * T_STRIDE + (uint32_t)(ks*32) + aoff;
                    ldm_x4(A_h + ra, ah4[ii][0], ah4[ii][1], ah4[ii][2], ah4[ii][3]);
                    ldm_x4(A_l + ra, al4[ii][0], al4[ii][1], al4[ii][2], al4[ii][3]);
                }
                // term-major passes: 8 independent accumulators per pass
                #pragma unroll
                for (int ii = 0; ii < 2; ii++)
                    #pragma unroll
                    for (int j = 0; j < 4; j++)
                        mma_bf16(acc[ip*2+ii][j], ah4[ii], bh[j]);
                #pragma unroll
                for (int ii = 0; ii < 2; ii++)
                    #pragma unroll
                    for (int j = 0; j < 4; j++)
                        mma_bf16(acc[ip*2+ii][j], ah4[ii], bl[j]);
                #pragma unroll
                for (int ii = 0; ii < 2; ii++)
                    #pragma unroll
                    for (int j = 0; j < 4; j++)
                        mma_bf16(acc[ip*2+ii][j], al4[ii], bh[j]);
            }
        }
        __syncthreads();
    }

    const int gid = lane >> 2, tig = lane & 3;
    float* Cfz = Cf ? (Cf + (size_t)kz * (size_t)Mc * (size_t)ldc) : Cf;
    const bool addb = (bias != nullptr) && (kz == 0);
    #pragma unroll
    for (int i = 0; i < 4; i++){
        #pragma unroll
        for (int j = 0; j < 4; j++){
            const int col = n0 + warpN*32 + j*8 + tig*2;
            float b0 = addb ? bias[col]     : 0.f;
            float b1 = addb ? bias[col + 1] : 0.f;
            const float qs = (epi == 2 && col < Dc) ? 0.125f : 1.0f;
            #pragma unroll
            for (int half = 0; half < 2; half++){
                const int row = m0 + warpM*64 + i*16 + gid + half*8;
                float v0 = acc[i][j][half*2 + 0] + b0;
                float v1 = acc[i][j][half*2 + 1] + b1;
                if (epi == 1){
                    v0 = 0.5f * v0 * (1.0f + erff(v0 * 0.70710678118654752f));
                    v1 = 0.5f * v1 * (1.0f + erff(v1 * 0.70710678118654752f));
                } else if (epi == 2){
                    v0 *= qs; v1 *= qs;
                }
                const size_t off = (size_t)row * ldc + col;
                if (Cfz) *(float2*)(Cfz + off) = make_float2(v0, v1);
                if (Ch){
                    uint32_t lo, hi = split_pack(v0, v1, lo);
                    *(uint32_t*)(Ch + off) = hi;
                    *(uint32_t*)(Cl + off) = lo;
                }
            }
        }
    }
}

// ---------------------------------------------------------------------------
// Flash attention via mma.sync (causal). Q pre-scaled by 0.125 at QKV epilogue.
// S and PV loops interleave the two acc quads per jj (shorter RAW chains).
// ---------------------------------------------------------------------------
#define AT_STRIDE 144
#define KV_STAGE  36864
#define FQ_H      36864
#define FQ_L      46080
#define FA2_SMEM  73728

__global__ void __launch_bounds__(128) flash_attn_mma(
    const __nv_bfloat16* __restrict__ qkvh, const __nv_bfloat16* __restrict__ qkvl,
    __nv_bfloat16* __restrict__ aoh, __nv_bfloat16* __restrict__ aol)
{
    extern __shared__ char smem[];
    const uint32_t sbase = smem_u32(smem);
    const int tid = threadIdx.x;
    const int wid = tid >> 5, lane = tid & 31;
    const int gid = lane >> 2, tig = lane & 3;
    const int bh = blockIdx.y;
    const int b = bh / Hc, h = bh - b*Hc;
    const int qt = (int)gridDim.x - 1 - (int)blockIdx.x;
    const int q0 = qt * 64;
    const size_t rowb = (size_t)b * Sc;
    const int qcol = h*64, kcol = Dc + h*64, vcol = 2*Dc + h*64;

    auto load_kv = [&](int kt, int s){
        const int k0 = kt * 64;
        const __nv_bfloat16* srcs[4] = {qkvh, qkvl, qkvh, qkvl};
        const int cols[4] = {kcol, kcol, vcol, vcol};
        #pragma unroll
        for (int i = 0; i < 16; i++){
            int idx = tid + i*128;
            int arr = idx >> 9;
            int rem = idx & 511;
            int row = rem >> 3, ch = rem & 7;
            const char* src = (const char*)(srcs[arr] + (rowb + k0 + row)*QKVc + cols[arr]) + ch*16;
            cpasync16(sbase + s*KV_STAGE + arr*9216 + row*AT_STRIDE + ch*16, src);
        }
        CP_COMMIT();
    };

    {
        #pragma unroll
        for (int i = 0; i < 8; i++){
            int idx = tid + i*128;
            int arr = idx >> 9;
            int rem = idx & 511;
            int row = rem >> 3, ch = rem & 7;
            const __nv_bfloat16* sp = arr ? qkvl : qkvh;
            const char* src = (const char*)(sp + (rowb + q0 + row)*QKVc + qcol) + ch*16;
            cpasync16(sbase + (arr ? FQ_L : FQ_H) + row*AT_STRIDE + ch*16, src);
        }
        load_kv(0, 0);
    }
    asm volatile("cp.async.wait_group 0;" ::: "memory");
    __syncthreads();

    uint32_t qhf[4][4], qlf[4][4];
    {
        const uint32_t ao_ = (uint32_t)(lane & 15)*AT_STRIDE + (uint32_t)(lane >> 4)*16;
        #pragma unroll
        for (int ks = 0; ks < 4; ks++){
            uint32_t ra = (uint32_t)(wid*16)*AT_STRIDE + (uint32_t)(ks*32) + ao_;
            ldm_x4(sbase + FQ_H + ra, qhf[ks][0], qhf[ks][1], qhf[ks][2], qhf[ks][3]);
            ldm_x4(sbase + FQ_L + ra, qlf[ks][0], qlf[ks][1], qlf[ks][2], qlf[ks][3]);
        }
    }
    __syncthreads();

    float accO[8][4];
    #pragma unroll
    for (int j = 0; j < 8; j++)
        #pragma unroll
        for (int c = 0; c < 4; c++) accO[j][c] = 0.f;
    float m_run[2] = {-1e30f, -1e30f};
    float l_run[2] = {0.f, 0.f};

    const uint32_t boff4 = (uint32_t)((lane & 7) + ((lane >> 4) << 3))*AT_STRIDE
                         + (uint32_t)((lane >> 3) & 1)*16;
    const uint32_t voff4 = (uint32_t)(lane & 15)*AT_STRIDE + (uint32_t)(lane >> 4)*16;

    const int row0 = q0 + wid*16 + gid;
    const int row1 = row0 + 8;

    for (int kt = 0; kt <= qt; kt++){
        const int s = kt & 1;
        if (kt > 0){
            asm volatile("cp.async.wait_group 0;" ::: "memory");
            __syncthreads();
        }
        if (kt < qt) load_kv(kt + 1, s ^ 1);

        const uint32_t K_h = sbase + s*KV_STAGE;
        const uint32_t K_l = K_h + 9216;
        const uint32_t V_h = K_h + 18432;
        const uint32_t V_l = K_h + 27648;

        float accS[8][4];
        #pragma unroll
        for (int j = 0; j < 8; j++)
            #pragma unroll
            for (int c = 0; c < 4; c++) accS[j][c] = 0.f;

        // S = Q K^T (3 terms), acc quads interleaved per jj
        #pragma unroll
        for (int ks = 0; ks < 4; ks++){
            #pragma unroll
            for (int jj = 0; jj < 4; jj++){
                uint32_t rb = (uint32_t)(jj*16)*AT_STRIDE + (uint32_t)(ks*32) + boff4;
                uint32_t bh4[4], bl4[4];
                ldm_x4(K_h + rb, bh4[0], bh4[1], bh4[2], bh4[3]);
                ldm_x4(K_l + rb, bl4[0], bl4[1], bl4[2], bl4[3]);
                mma_bf16(accS[2*jj],   qhf[ks], bh4 + 0);
                mma_bf16(accS[2*jj+1], qhf[ks], bh4 + 2);
                mma_bf16(accS[2*jj],   qhf[ks], bl4 + 0);
                mma_bf16(accS[2*jj+1], qhf[ks], bl4 + 2);
                mma_bf16(accS[2*jj],   qlf[ks], bh4 + 0);
                mma_bf16(accS[2*jj+1], qlf[ks], bh4 + 2);
            }
        }

        // causal mask on diagonal tile (Q already carries the 1/8 scale)
        const bool diag = (kt == qt);
        const int k0 = kt * 64;
        if (diag){
            #pragma unroll
            for (int j = 0; j < 8; j++){
                #pragma unroll
                for (int c = 0; c < 4; c++){
                    int col = k0 + j*8 + tig*2 + (c & 1);
                    int row = (c < 2) ? row0 : row1;
                    if (col > row) accS[j][c] = -1e30f;
                }
            }
        }

        #pragma unroll
        for (int half = 0; half < 2; half++){
            float mloc = -1e30f;
            #pragma unroll
            for (int j = 0; j < 8; j++){
                mloc = fmaxf(mloc, accS[j][half*2]);
                mloc = fmaxf(mloc, accS[j][half*2+1]);
            }
            mloc = fmaxf(mloc, __shfl_xor_sync(0xFFFFFFFFu, mloc, 1));
            mloc = fmaxf(mloc, __shfl_xor_sync(0xFFFFFFFFu, mloc, 2));
            const float mnew = fmaxf(m_run[half], mloc);
            const float alpha = __expf(m_run[half] - mnew);
            m_run[half] = mnew;
            float psum = 0.f;
            #pragma unroll
            for (int j = 0; j < 8; j++){
                float p0 = __expf(accS[j][half*2]   - mnew);
                float p1 = __expf(accS[j][half*2+1] - mnew);
                accS[j][half*2]   = p0;
                accS[j][half*2+1] = p1;
                psum += p0 + p1;
            }
            psum += __shfl_xor_sync(0xFFFFFFFFu, psum, 1);
            psum += __shfl_xor_sync(0xFFFFFFFFu, psum, 2);
            l_run[half] = l_run[half]*alpha + psum;
            #pragma unroll
            for (int j = 0; j < 8; j++){
                accO[j][half*2]   *= alpha;
                accO[j][half*2+1] *= alpha;
            }
        }

        // O += P V (3 terms), acc quads interleaved per jj
        #pragma unroll
        for (int ks = 0; ks < 4; ks++){
            uint32_t aPh[4], aPl[4];
            #pragma unroll
            for (int t = 0; t < 4; t++){
                const int j = 2*ks + (t >> 1);
                const int c0 = (t & 1)*2;
                aPh[t] = split_pack(accS[j][c0], accS[j][c0+1], aPl[t]);
            }
            #pragma unroll
            for (int jj = 0; jj < 4; jj++){
                uint32_t rv = (uint32_t)(ks*16)*AT_STRIDE + (uint32_t)(jj*32) + voff4;
                uint32_t vh4[4], vl4[4];
                ldm_x4_t(V_h + rv, vh4[0], vh4[1], vh4[2], vh4[3]);
                ldm_x4_t(V_l + rv, vl4[0], vl4[1], vl4[2], vl4[3]);
                mma_bf16(accO[2*jj],   aPh, vh4 + 0);
                mma_bf16(accO[2*jj+1], aPh, vh4 + 2);
                mma_bf16(accO[2*jj],   aPh, vl4 + 0);
                mma_bf16(accO[2*jj+1], aPh, vl4 + 2);
                mma_bf16(accO[2*jj],   aPl, vh4 + 0);
                mma_bf16(accO[2*jj+1], aPl, vh4 + 2);
            }
        }
    }

    const float rl0 = 1.0f / l_run[0];
    const float rl1 = 1.0f / l_run[1];
    #pragma unroll
    for (int j = 0; j < 8; j++){
        const int col = h*64 + j*8 + tig*2;
        const size_t o0 = (rowb + row0)*Dc + col;
        const size_t o1 = (rowb + row1)*Dc + col;
        uint32_t lo, hi;
        hi = split_pack(accO[j][0]*rl0, accO[j][1]*rl0, lo);
        *(uint32_t*)(aoh + o0) = hi; *(uint32_t*)(aol + o0) = lo;
        hi = split_pack(accO[j][2]*rl1, accO[j][3]*rl1, lo);
        *(uint32_t*)(aoh + o1) = hi; *(uint32_t*)(aol + o1) = lo;
    }
}

// ---------------------------------------------------------------------------
// Fused weight prep (one launch, all layers/matrices)
// ---------------------------------------------------------------------------
#define TSB_PER_LAYER 6912

__global__ void __launch_bounds__(256) transpose_split_all(
    const float* __restrict__ Wq, const float* __restrict__ Wk,
    const float* __restrict__ Wv, const float* __restrict__ Wo,
    const float* __restrict__ W1, const float* __restrict__ W2,
    __nv_bfloat16* __restrict__ gh_, __nv_bfloat16* __restrict__ gl_)
{
    const size_t DD = (size_t)Dc*Dc, DF = (size_t)Dc*Fc;
    int l = blockIdx.x / TSB_PER_LAYER;
    int r = blockIdx.x - l*TSB_PER_LAYER;

    const float* src; size_t dst; int K, N, bx, by;
    if (r < 2304){
        int m = r / 576, t = r - m*576;
        const float* Ws[4] = {Wq, Wk, Wv, Wo};
        src = Ws[m] + (size_t)l*DD; dst = (size_t)l*WT_PER_LAYER + (size_t)m*DD;
        K = Dc; N = Dc; by = t / 24; bx = t - by*24;
    } else if (r < 4608){
        int t = r - 2304;
        src = W1 + (size_t)l*DF; dst = (size_t)l*WT_PER_LAYER + 4*DD;
        K = Dc; N = Fc; by = t / 96; bx = t - by*96;
    } else {
        int t = r - 4608;
        src = W2 + (size_t)l*DF; dst = (size_t)l*WT_PER_LAYER + 4*DD + DF;
        K = Fc; N = Dc; by = t / 24; bx = t - by*24;
    }

    __shared__ float t[32][33];
    const int kb = by*32, nb = bx*32;
    const int x = threadIdx.x & 31, y = (threadIdx.x >> 5) * 4;
    #pragma unroll
    for (int i = 0; i < 4; i++)
        t[y+i][x] = src[(size_t)(kb + y + i)*N + nb + x];
    __syncthreads();
    #pragma unroll
    for (int i = 0; i < 4; i++){
        float v = t[x][y+i];
        __nv_bfloat16 h = __float2bfloat16(v);
        float lo = v - __bfloat162float(h);
        gh_[dst + (size_t)(nb + y + i)*K + kb + x] = h;
        gl_[dst + (size_t)(nb + y + i)*K + kb + x] = __float2bfloat16(lo);
    }
}

// ---------------------------------------------------------------------------
// Activation bf16 split — initial x only
// ---------------------------------------------------------------------------
__global__ void __launch_bounds__(256) split_act(
    const float* __restrict__ in, __nv_bfloat16* __restrict__ oh,
    __nv_bfloat16* __restrict__ ol, int n)
{
    int i = blockIdx.x * 1024 + threadIdx.x * 4;
    if (i >= n) return;
    float4 v = *(const float4*)(in + i);
    float vv[4] = {v.x, v.y, v.z, v.w};
    __nv_bfloat16 h[4], l[4];
    #pragma unroll
    for (int j = 0; j < 4; j++){
        h[j] = __float2bfloat16(vv[j]);
        l[j] = __float2bfloat16(vv[j] - __bfloat162float(h[j]));
    }
    *(uint2*)(oh + i) = *(uint2*)h;
    *(uint2*)(ol + i) = *(uint2*)l;
}

// ---------------------------------------------------------------------------
// out = LayerNorm(res + ya + yb) * g + b  -> fp32 out + split bf16
// ---------------------------------------------------------------------------
__global__ void __launch_bounds__(256) add_ln(
    const float* __restrict__ res, const float* __restrict__ ya,
    const float* __restrict__ yb,
    const float* __restrict__ gw, const float* __restrict__ bw,
    float* __restrict__ out,
    __nv_bfloat16* __restrict__ oh, __nv_bfloat16* __restrict__ ol)
{
    const int row = blockIdx.x;
    const float* r  = res + (size_t)row * Dc;
    const float* a  = ya  + (size_t)row * Dc;
    const float* bb = yb  + (size_t)row * Dc;
    float v[3];
    float s = 0.f, s2 = 0.f;
    #pragma unroll
    for (int qq = 0; qq < 3; qq++) {
        int idx = threadIdx.x + qq*256;
        float t = r[idx] + a[idx] + bb[idx];
        v[qq] = t; s += t; s2 += t*t;
    }
    #pragma unroll
    for (int off = 16; off; off >>= 1) {
        s  += __shfl_xor_sync(0xFFFFFFFFu, s,  off);
        s2 += __shfl_xor_sync(0xFFFFFFFFu, s2, off);
    }
    __shared__ float sh[2][8];
    const int w = threadIdx.x >> 5, lane = threadIdx.x & 31;
    if (lane == 0) { sh[0][w] = s; sh[1][w] = s2; }
    __syncthreads();
    float ts = 0.f, ts2 = 0.f;
    #pragma unroll
    for (int i = 0; i < 8; i++) { ts += sh[0][i]; ts2 += sh[1][i]; }
    const float mu  = ts  * (1.0f/768.0f);
    const float var = ts2 * (1.0f/768.0f) - mu*mu;
    const float rstd = rsqrtf(var + 1e-5f);
    #pragma unroll
    for (int qq = 0; qq < 3; qq++) {
        int idx = threadIdx.x + qq*256;
        float o = (v[qq] - mu) * rstd * gw[idx] + bw[idx];
        const size_t off = (size_t)row*Dc + idx;
        out[off] = o;
        __nv_bfloat16 hh = __float2bfloat16(o);
        oh[off] = hh;
        ol[off] = __float2bfloat16(o - __bfloat162float(hh));
    }
}

// ---------------------------------------------------------------------------
// Host launcher
// ---------------------------------------------------------------------------
extern "C" void kernel_launch(void* const* d_in, const int* in_sizes, int n_in,
                              void* d_out, int out_size)
{
    const float* x    = (const float*)d_in[0];
    const float* Wq   = (const float*)d_in[2];
    const float* Wk   = (const float*)d_in[3];
    const float* Wv   = (const float*)d_in[4];
    const float* Wo   = (const float*)d_in[5];
    const float* bo   = (const float*)d_in[6];
    const float* ln1g = (const float*)d_in[7];
    const float* ln1b = (const float*)d_in[8];
    const float* W1   = (const float*)d_in[9];
    const float* b1   = (const float*)d_in[10];
    const float* W2   = (const float*)d_in[11];
    const float* b2   = (const float*)d_in[12];
    const float* ln2g = (const float*)d_in[13];
    const float* ln2b = (const float*)d_in[14];

    float *gx, *gproj, *gh, *gf2;
    __nv_bfloat16 *acth, *actl, *qkvh, *qkvl, *f1h, *f1l, *wh, *wl;
    cudaGetSymbolAddress((void**)&gx,    g_x);
    cudaGetSymbolAddress((void**)&gproj, g_proj);
    cudaGetSymbolAddress((void**)&gh,    g_h);
    cudaGetSymbolAddress((void**)&gf2,   g_f2);
    cudaGetSymbolAddress((void**)&acth,  g_acth);
    cudaGetSymbolAddress((void**)&actl,  g_actl);
    cudaGetSymbolAddress((void**)&qkvh,  g_qkvh);
    cudaGetSymbolAddress((void**)&qkvl,  g_qkvl);
    cudaGetSymbolAddress((void**)&f1h,   g_f1h);
    cudaGetSymbolAddress((void**)&f1l,   g_f1l);
    cudaGetSymbolAddress((void**)&wh,    g_wt_hi);
    cudaGetSymbolAddress((void**)&wl,    g_wt_lo);

    cudaFuncSetAttribute(gemm_tc,        cudaFuncAttributeMaxDynamicSharedMemorySize, GSM_TOTAL);
    cudaFuncSetAttribute(flash_attn_mma, cudaFuncAttributeMaxDynamicSharedMemorySize, FA2_SMEM);

    const size_t DD = (size_t)Dc*Dc, DF = (size_t)Dc*Fc;
    const size_t MD = (size_t)Mc*Dc;

    transpose_split_all<<<TSB_PER_LAYER*Lc, 256>>>(Wq, Wk, Wv, Wo, W1, W2, wh, wl);

    cudaMemcpyAsync(gx, x, MD*sizeof(float), cudaMemcpyDeviceToDevice);
    split_act<<<(Mc*Dc)/1024, 256>>>(gx, acth, actl, Mc*Dc);

    const dim3 gQKV(QKVc/128, Mc/128);      // (18, 64)
    const dim3 gDs(Dc/128, Mc/128, 2);      // (6, 64, 2) split-K=2
    const dim3 gF(Fc/128, Mc/128);          // (24, 64)

    for (int l = 0; l < Lc; l++){
        size_t wb = (size_t)l * WT_PER_LAYER;
        const __nv_bfloat16 *qkvw_h = wh+wb,      *qkvw_l = wl+wb;
        const __nv_bfloat16 *ohw = wh+wb+3*DD,    *olw = wl+wb+3*DD;
        const __nv_bfloat16 *w1h = wh+wb+4*DD,    *w1l = wl+wb+4*DD;
        const __nv_bfloat16 *w2h = wh+wb+4*DD+DF, *w2l = wl+wb+4*DD+DF;

        // QKV: epi=2 scales q-columns by 0.125 (folded softmax scale)
        gemm_tc<<<gQKV, 256, GSM_TOTAL>>>(acth, actl, qkvw_h, qkvw_l, nullptr,
                                          nullptr, qkvh, qkvl, Mc, QKVc, Dc, QKVc, 2, 1);
        flash_attn_mma<<<dim3(Sc/64, Bc*Hc), 128, FA2_SMEM>>>(qkvh, qkvl, acth, actl);
        gemm_tc<<<gDs, 256, GSM_TOTAL>>>(acth, actl, ohw, olw, bo + (size_t)l*Dc,
                                         gproj, nullptr, nullptr, Mc, Dc, Dc, Dc, 0, 2);
        add_ln<<<Mc, 256>>>(gx, gproj, gproj + MD,
                            ln1g + (size_t)l*Dc, ln1b + (size_t)l*Dc, gh, acth, actl);
        gemm_tc<<<gF, 256, GSM_TOTAL>>>(acth, actl, w1h, w1l, b1 + (size_t)l*Fc,
                                        nullptr, f1h, f1l, Mc, Fc, Dc, Fc, 1, 1);
        gemm_tc<<<gDs, 256, GSM_TOTAL>>>(f1h, f1l, w2h, w2l, b2 + (size_t)l*Dc,
                                         gf2, nullptr, nullptr, Mc, Dc, Fc, Dc, 0, 2);
        add_ln<<<Mc, 256>>>(gh, gf2, gf2 + MD,
                            ln2g + (size_t)l*Dc, ln2b + (size_t)l*Dc, gx, acth, actl);
    }

    cudaMemcpyAsync(d_out, gx, MD*sizeof(float), cudaMemcpyDeviceToDevice);
}